// round 1
// baseline (speedup 1.0000x reference)
#include <cuda_runtime.h>
#include <math.h>

#define VSZ 32000
#define ESZ 400
#define HSZ 1150
#define BSZ 16
#define TSZ 128
#define GP12 4608   // padded gate-row count for layers 1/2 (144 blocks * 32)
#define GP3  1600   // layer 3 gate rows (50 blocks * 32, exact)

// ---------------- scratch (device globals; no allocation allowed) ----------------
__device__ float g_y0[TSZ*BSZ*ESZ];
__device__ float g_y1[TSZ*BSZ*HSZ];
__device__ float g_y2[TSZ*BSZ*HSZ];
__device__ float g_y3[TSZ*BSZ*ESZ];
__device__ float g_pre[TSZ*BSZ*4*HSZ];
__device__ float g_Wt1[HSZ*GP12];
__device__ float g_Wt2[HSZ*GP12];
__device__ float g_Wt3[ESZ*GP3];
__device__ float g_hTa[HSZ*BSZ];
__device__ float g_hTb[HSZ*BSZ];
__device__ float g_cT1[HSZ*BSZ];
__device__ float g_cT2[HSZ*BSZ];
__device__ float g_cT3[ESZ*BSZ];

// ---------------- tiny utility kernels ----------------
__global__ void zero_k(float* __restrict__ p, int n) {
    int i = blockIdx.x * blockDim.x + threadIdx.x;
    if (i < n) p[i] = 0.f;
}

// y0[(t*B+b)*E + e] = emb[x[b*T+t]*E + e]
__global__ void embed_k(const float* __restrict__ emb, const int* __restrict__ x,
                        float* __restrict__ y0) {
    int idx = blockIdx.x * blockDim.x + threadIdx.x;
    if (idx >= TSZ * BSZ * ESZ) return;
    int e  = idx % ESZ;
    int tb = idx / ESZ;
    int b  = tb % BSZ;
    int t  = tb / BSZ;
    y0[idx] = emb[(size_t)x[b * TSZ + t] * ESZ + e];
}

// Gate-permuted transpose of W_hh (4*Hp x Hp, row-major) into
// Wt[k*Gp + (jblk*32 + g*8 + u)] = W_hh[(g*Hp + jblk*8 + u)*Hp + k], zero-padded.
__global__ void wtrans_k(const float* __restrict__ W, float* __restrict__ Wt,
                         int Hp, int Gp) {
    __shared__ float tile[32][33];
    int jblk = blockIdx.x;
    int k0   = blockIdx.y * 32;
    // load 32 permuted rows x 32 k, coalesced along k
    for (int rr = 0; rr < 32; rr += 8) {
        int r = rr + threadIdx.y;
        int g = r >> 3, u = r & 7;
        int j = jblk * 8 + u;
        int orow = g * Hp + j;
        int k = k0 + threadIdx.x;
        tile[r][threadIdx.x] = (j < Hp && k < Hp) ? W[(size_t)orow * Hp + k] : 0.f;
    }
    __syncthreads();
    // store transposed: consecutive threadIdx.x -> consecutive permuted columns
    for (int kk = 0; kk < 32; kk += 8) {
        int k = k0 + kk + threadIdx.y;
        if (k < Hp)
            Wt[(size_t)k * Gp + jblk * 32 + threadIdx.x] = tile[threadIdx.x][kk + threadIdx.y];
    }
}

// ---------------- fp32 tiled GEMM:  C = A(MxK) * B(NxK)^T + bias ----------------
// BM=128, BN=64, BK=16, 256 threads, 8x4 per-thread microtile.
// mode 0: C[m*N+n] = v      (pre-activation buffers)
// mode 1: C[(b*N+n)*T + t] = v  with m = t*16+b   (logits, (B,V,T) layout)
__global__ __launch_bounds__(256)
void gemm_k(const float* __restrict__ A, const float* __restrict__ Bm,
            const float* __restrict__ bias1, const float* __restrict__ bias2,
            float* __restrict__ C, int M, int N, int K, int mode) {
    __shared__ float As[16][128];
    __shared__ float Bs[16][64];
    int m0 = blockIdx.y * 128;
    int n0 = blockIdx.x * 64;
    int tid = threadIdx.x;
    float acc[8][4];
#pragma unroll
    for (int i = 0; i < 8; i++)
#pragma unroll
        for (int j = 0; j < 4; j++) acc[i][j] = 0.f;

    int ty = tid >> 4;   // 0..15
    int tx = tid & 15;   // 0..15

    for (int k0 = 0; k0 < K; k0 += 16) {
#pragma unroll
        for (int i = 0; i < 8; i++) {
            int e = tid + i * 256;
            int m = e >> 4, k = e & 15;
            As[k][m] = (k0 + k < K) ? A[(size_t)(m0 + m) * K + k0 + k] : 0.f;
        }
#pragma unroll
        for (int i = 0; i < 4; i++) {
            int e = tid + i * 256;
            int n = e >> 4, k = e & 15;
            Bs[k][n] = (n0 + n < N && k0 + k < K) ? Bm[(size_t)(n0 + n) * K + k0 + k] : 0.f;
        }
        __syncthreads();
#pragma unroll
        for (int kk = 0; kk < 16; kk++) {
            float a[8], bv[4];
#pragma unroll
            for (int j = 0; j < 4; j++) {
                a[j]     = As[kk][ty * 4 + j];
                a[4 + j] = As[kk][64 + ty * 4 + j];
                bv[j]    = Bs[kk][tx * 4 + j];
            }
#pragma unroll
            for (int i = 0; i < 8; i++)
#pragma unroll
                for (int j = 0; j < 4; j++) acc[i][j] += a[i] * bv[j];
        }
        __syncthreads();
    }

#pragma unroll
    for (int i = 0; i < 8; i++) {
        int mloc = (i < 4) ? (ty * 4 + i) : (64 + ty * 4 + (i - 4));
        int m = m0 + mloc;
#pragma unroll
        for (int j = 0; j < 4; j++) {
            int n = n0 + tx * 4 + j;
            if (n < N) {
                float v = acc[i][j];
                if (bias1) v += bias1[n];
                if (bias2) v += bias2[n];
                if (mode == 0) {
                    C[(size_t)m * N + n] = v;
                } else {
                    int b = m & 15, t = m >> 4;
                    C[((size_t)b * N + n) * TSZ + t] = v;
                }
            }
        }
    }
}

// ---------------- fused LSTM step ----------------
// One CTA owns 8 hidden units * 4 gates (= 32 permuted weight columns), all 16 batches.
// 256 threads = 32 columns x 8 k-slices; smem reduction; then pointwise cell update.
__device__ __forceinline__ float sigf(float z) { return 1.f / (1.f + expf(-z)); }

__global__ __launch_bounds__(256)
void lstm_step_k(const float* __restrict__ pre, const float* __restrict__ Wt,
                 const float* __restrict__ hin, float* __restrict__ hout,
                 float* __restrict__ cT, float* __restrict__ y,
                 int Hp, int Gp, int t) {
    int r = threadIdx.x & 31;   // permuted column within block: g*8+u
    int s = threadIdx.x >> 5;   // k-slice 0..7
    int col = blockIdx.x * 32 + r;

    float acc[16];
#pragma unroll
    for (int i = 0; i < 16; i++) acc[i] = 0.f;

    const float4* hv4 = (const float4*)hin;  // hin[k*16 + b]
#pragma unroll 2
    for (int k = s; k < Hp; k += 8) {
        float w = Wt[(size_t)k * Gp + col];
        float4 h0 = hv4[k * 4 + 0];
        float4 h1 = hv4[k * 4 + 1];
        float4 h2 = hv4[k * 4 + 2];
        float4 h3 = hv4[k * 4 + 3];
        acc[0]  += w * h0.x; acc[1]  += w * h0.y; acc[2]  += w * h0.z; acc[3]  += w * h0.w;
        acc[4]  += w * h1.x; acc[5]  += w * h1.y; acc[6]  += w * h1.z; acc[7]  += w * h1.w;
        acc[8]  += w * h2.x; acc[9]  += w * h2.y; acc[10] += w * h2.z; acc[11] += w * h2.w;
        acc[12] += w * h3.x; acc[13] += w * h3.y; acc[14] += w * h3.z; acc[15] += w * h3.w;
    }

    __shared__ float red[8][32][16];
    float4* rp = (float4*)&red[s][r][0];
    rp[0] = make_float4(acc[0], acc[1], acc[2], acc[3]);
    rp[1] = make_float4(acc[4], acc[5], acc[6], acc[7]);
    rp[2] = make_float4(acc[8], acc[9], acc[10], acc[11]);
    rp[3] = make_float4(acc[12], acc[13], acc[14], acc[15]);
    __syncthreads();

    if (threadIdx.x < 128) {
        int u = threadIdx.x >> 4;   // unit within block
        int b = threadIdx.x & 15;   // batch
        int j = blockIdx.x * 8 + u;
        if (j < Hp) {
            int G = 4 * Hp;
            const float* prow = pre + ((size_t)(t * 16 + b)) * G + j;
            float gv[4];
#pragma unroll
            for (int g = 0; g < 4; g++) {
                float sum = prow[(size_t)g * Hp];
#pragma unroll
                for (int s2 = 0; s2 < 8; s2++) sum += red[s2][g * 8 + u][b];
                gv[g] = sum;
            }
            float ig = sigf(gv[0]);
            float fg = sigf(gv[1]);
            float gg = tanhf(gv[2]);
            float og = sigf(gv[3]);
            float c  = fg * cT[j * 16 + b] + ig * gg;
            float hn = og * tanhf(c);
            cT[j * 16 + b]   = c;
            hout[j * 16 + b] = hn;
            y[((size_t)(t * 16 + b)) * Hp + j] = hn;
        }
    }
}

// ---------------- finalize: pack h1..h3, c1..c3 behind logits ----------------
__global__ void finalize_k(const float* __restrict__ y1, const float* __restrict__ y2,
                           const float* __restrict__ y3, const float* __restrict__ cT1,
                           const float* __restrict__ cT2, const float* __restrict__ cT3,
                           float* __restrict__ out) {
    int i = blockIdx.x * blockDim.x + threadIdx.x;
    if (i >= 86400) return;
    const size_t O = (size_t)BSZ * VSZ * TSZ;
    if (i < 18400) {
        int b = i / 1150, j = i % 1150;
        out[O + i] = y1[((size_t)(127 * 16 + b)) * 1150 + j];
    } else if (i < 36800) {
        int k = i - 18400; int b = k / 1150, j = k % 1150;
        out[O + i] = y2[((size_t)(127 * 16 + b)) * 1150 + j];
    } else if (i < 43200) {
        int k = i - 36800; int b = k / 400, j = k % 400;
        out[O + i] = y3[((size_t)(127 * 16 + b)) * 400 + j];
    } else if (i < 61600) {
        int k = i - 43200; int j = (k % 1150), b = k / 1150;
        out[O + i] = cT1[j * 16 + b];
    } else if (i < 80000) {
        int k = i - 61600; int j = (k % 1150), b = k / 1150;
        out[O + i] = cT2[j * 16 + b];
    } else {
        int k = i - 80000; int j = (k % 400), b = k / 400;
        out[O + i] = cT3[j * 16 + b];
    }
}

// ---------------- launch ----------------
extern "C" void kernel_launch(void* const* d_in, const int* in_sizes, int n_in,
                              void* d_out, int out_size) {
    const float* emb  = (const float*)d_in[0];
    const float* Wih1 = (const float*)d_in[1];
    const float* Whh1 = (const float*)d_in[2];
    const float* bih1 = (const float*)d_in[3];
    const float* bhh1 = (const float*)d_in[4];
    const float* Wih2 = (const float*)d_in[5];
    const float* Whh2 = (const float*)d_in[6];
    const float* bih2 = (const float*)d_in[7];
    const float* bhh2 = (const float*)d_in[8];
    const float* Wih3 = (const float*)d_in[9];
    const float* Whh3 = (const float*)d_in[10];
    const float* bih3 = (const float*)d_in[11];
    const float* bhh3 = (const float*)d_in[12];
    const float* linb = (const float*)d_in[13];
    const int*   x    = (const int*)d_in[14];
    float* out = (float*)d_out;

    float *y0, *y1, *y2, *y3, *pre, *Wt1, *Wt2, *Wt3, *hTa, *hTb, *cT1, *cT2, *cT3;
    cudaGetSymbolAddress((void**)&y0,  g_y0);
    cudaGetSymbolAddress((void**)&y1,  g_y1);
    cudaGetSymbolAddress((void**)&y2,  g_y2);
    cudaGetSymbolAddress((void**)&y3,  g_y3);
    cudaGetSymbolAddress((void**)&pre, g_pre);
    cudaGetSymbolAddress((void**)&Wt1, g_Wt1);
    cudaGetSymbolAddress((void**)&Wt2, g_Wt2);
    cudaGetSymbolAddress((void**)&Wt3, g_Wt3);
    cudaGetSymbolAddress((void**)&hTa, g_hTa);
    cudaGetSymbolAddress((void**)&hTb, g_hTb);
    cudaGetSymbolAddress((void**)&cT1, g_cT1);
    cudaGetSymbolAddress((void**)&cT2, g_cT2);
    cudaGetSymbolAddress((void**)&cT3, g_cT3);

    const int M = TSZ * BSZ;  // 2048

    // embedding + weight transposes + cell-state zeroing
    embed_k<<<(TSZ * BSZ * ESZ + 255) / 256, 256>>>(emb, x, y0);
    wtrans_k<<<dim3(GP12 / 32, (HSZ + 31) / 32), dim3(32, 8)>>>(Whh1, Wt1, HSZ, GP12);
    wtrans_k<<<dim3(GP12 / 32, (HSZ + 31) / 32), dim3(32, 8)>>>(Whh2, Wt2, HSZ, GP12);
    wtrans_k<<<dim3(GP3 / 32, (ESZ + 31) / 32), dim3(32, 8)>>>(Whh3, Wt3, ESZ, GP3);
    zero_k<<<(HSZ * BSZ + 255) / 256, 256>>>(cT1, HSZ * BSZ);
    zero_k<<<(HSZ * BSZ + 255) / 256, 256>>>(cT2, HSZ * BSZ);
    zero_k<<<(ESZ * BSZ + 255) / 256, 256>>>(cT3, ESZ * BSZ);

    // ----- layer 1 -----
    gemm_k<<<dim3((4 * HSZ + 63) / 64, M / 128), 256>>>(y0, Wih1, bih1, bhh1, pre,
                                                        M, 4 * HSZ, ESZ, 0);
    zero_k<<<(HSZ * BSZ + 255) / 256, 256>>>(hTa, HSZ * BSZ);
    for (int t = 0; t < TSZ; t++) {
        float* hin  = (t & 1) ? hTb : hTa;
        float* hout = (t & 1) ? hTa : hTb;
        lstm_step_k<<<GP12 / 32, 256>>>(pre, Wt1, hin, hout, cT1, y1, HSZ, GP12, t);
    }

    // ----- layer 2 -----
    gemm_k<<<dim3((4 * HSZ + 63) / 64, M / 128), 256>>>(y1, Wih2, bih2, bhh2, pre,
                                                        M, 4 * HSZ, HSZ, 0);
    zero_k<<<(HSZ * BSZ + 255) / 256, 256>>>(hTa, HSZ * BSZ);
    for (int t = 0; t < TSZ; t++) {
        float* hin  = (t & 1) ? hTb : hTa;
        float* hout = (t & 1) ? hTa : hTb;
        lstm_step_k<<<GP12 / 32, 256>>>(pre, Wt2, hin, hout, cT2, y2, HSZ, GP12, t);
    }

    // ----- layer 3 -----
    gemm_k<<<dim3((4 * ESZ + 63) / 64, M / 128), 256>>>(y2, Wih3, bih3, bhh3, pre,
                                                        M, 4 * ESZ, HSZ, 0);
    zero_k<<<(ESZ * BSZ + 255) / 256, 256>>>(hTa, ESZ * BSZ);
    for (int t = 0; t < TSZ; t++) {
        float* hin  = (t & 1) ? hTb : hTa;
        float* hout = (t & 1) ? hTa : hTb;
        lstm_step_k<<<GP3 / 32, 256>>>(pre, Wt3, hin, hout, cT3, y3, ESZ, GP3, t);
    }

    // ----- tied output projection into (B,V,T) -----
    gemm_k<<<dim3(VSZ / 64, M / 128), 256>>>(y3, emb, linb, nullptr, out,
                                             M, VSZ, ESZ, 1);

    // ----- final states -----
    finalize_k<<<(86400 + 255) / 256, 256>>>(y1, y2, y3, cT1, cT2, cT3, out);
}

// round 2
// speedup vs baseline: 1.1359x; 1.1359x over previous
#include <cuda_runtime.h>
#include <math.h>

#define VSZ 32000
#define ESZ 400
#define HSZ 1150
#define HPAD 1152
#define BSZ 16
#define TSZ 128
#define GP12 4608   // padded gate-row count for layers 1/2 (144 blocks * 32)
#define GP3  1600   // layer 3 gate rows (50 blocks * 32, exact)

// ---------------- scratch (device globals; no allocation allowed) ----------------
__device__ float g_y0[TSZ*BSZ*ESZ];
__device__ float g_y1[TSZ*BSZ*HPAD];
__device__ float g_y2[TSZ*BSZ*HPAD];
__device__ float g_y3[TSZ*BSZ*ESZ];
__device__ float g_pre[TSZ*BSZ*4*HSZ];
__device__ float g_Wt1[HSZ*GP12];
__device__ float g_Wt2[HSZ*GP12];
__device__ float g_Wt3[ESZ*GP3];
__device__ float g_Wih2p[4*HSZ*HPAD];
__device__ float g_Wih3p[4*ESZ*HPAD];
__device__ float g_hTa[HSZ*BSZ];
__device__ float g_hTb[HSZ*BSZ];
__device__ float g_cT1[HSZ*BSZ];
__device__ float g_cT2[HSZ*BSZ];
__device__ float g_cT3[ESZ*BSZ];

// ---------------- tiny utility kernels ----------------
__global__ void zero_k(float* __restrict__ p, int n) {
    int i = blockIdx.x * blockDim.x + threadIdx.x;
    if (i < n) p[i] = 0.f;
}

// pad rows: dst (rows x Kout) = src (rows x Kin) zero-extended
__global__ void pad_k(const float* __restrict__ src, float* __restrict__ dst,
                      int rows, int Kin, int Kout) {
    int idx = blockIdx.x * blockDim.x + threadIdx.x;
    if (idx >= rows * Kout) return;
    int r = idx / Kout, k = idx % Kout;
    dst[idx] = (k < Kin) ? src[(size_t)r * Kin + k] : 0.f;
}

// y0[(b*T+t)*E + e] = emb[x[b*T+t]*E + e]   (row = b*T+t directly matches x index)
__global__ void embed_k(const float* __restrict__ emb, const int* __restrict__ x,
                        float* __restrict__ y0) {
    int idx = blockIdx.x * blockDim.x + threadIdx.x;
    if (idx >= TSZ * BSZ * ESZ) return;
    int e   = idx % ESZ;
    int row = idx / ESZ;      // b*T + t
    y0[idx] = emb[(size_t)x[row] * ESZ + e];
}

// Gate-permuted transpose of W_hh (4*Hp x Hp, row-major) into
// Wt[k*Gp + (jblk*32 + g*8 + u)] = W_hh[(g*Hp + jblk*8 + u)*Hp + k], zero-padded.
__global__ void wtrans_k(const float* __restrict__ W, float* __restrict__ Wt,
                         int Hp, int Gp) {
    __shared__ float tile[32][33];
    int jblk = blockIdx.x;
    int k0   = blockIdx.y * 32;
    for (int rr = 0; rr < 32; rr += 8) {
        int r = rr + threadIdx.y;
        int g = r >> 3, u = r & 7;
        int j = jblk * 8 + u;
        int orow = g * Hp + j;
        int k = k0 + threadIdx.x;
        tile[r][threadIdx.x] = (j < Hp && k < Hp) ? W[(size_t)orow * Hp + k] : 0.f;
    }
    __syncthreads();
    for (int kk = 0; kk < 32; kk += 8) {
        int k = k0 + kk + threadIdx.y;
        if (k < Hp)
            Wt[(size_t)k * Gp + jblk * 32 + threadIdx.x] = tile[threadIdx.x][kk + threadIdx.y];
    }
}

// ---------------- fp32 SGEMM:  C = A(MxK) * B(NxK)^T + bias ----------------
// BM=BN=128, BK=8, 256 threads, 8x8 microtile, float4 loads, double-buffered smem.
// Requirements: M % 128 == 0, K % 8 == 0, K % 4 == 0 (float4), N % 4 == 0.
// mode 0: C[m*N + n] = v
// mode 1: C[((b*N + n)*T) + t] = v  with m = b*T + t (one b per m-block since T=128)
__global__ __launch_bounds__(256)
void gemm_k(const float* __restrict__ A, const float* __restrict__ Bm,
            const float* __restrict__ bias1, const float* __restrict__ bias2,
            float* __restrict__ C, int M, int N, int K, int mode) {
    __shared__ float As[2][8][128];
    __shared__ float Bs[2][8][128];

    const int tid = threadIdx.x;
    const int ty = tid >> 4;          // 0..15
    const int tx = tid & 15;          // 0..15
    const int lrow = tid >> 1;        // 0..127
    const int lcol = (tid & 1) * 4;   // 0 or 4

    const int m0 = blockIdx.y * 128;
    const int n0 = blockIdx.x * 128;

    const float* Aptr = A + (size_t)(m0 + lrow) * K + lcol;
    const float* Bptr = Bm + (size_t)(n0 + lrow) * K + lcol;
    const bool bvalid = (n0 + lrow) < N;

    // prologue
    {
        float4 av = *(const float4*)Aptr;
        float4 bv = bvalid ? *(const float4*)Bptr : make_float4(0.f, 0.f, 0.f, 0.f);
        As[0][lcol + 0][lrow] = av.x; As[0][lcol + 1][lrow] = av.y;
        As[0][lcol + 2][lrow] = av.z; As[0][lcol + 3][lrow] = av.w;
        Bs[0][lcol + 0][lrow] = bv.x; Bs[0][lcol + 1][lrow] = bv.y;
        Bs[0][lcol + 2][lrow] = bv.z; Bs[0][lcol + 3][lrow] = bv.w;
    }
    __syncthreads();

    float acc[8][8];
#pragma unroll
    for (int i = 0; i < 8; i++)
#pragma unroll
        for (int j = 0; j < 8; j++) acc[i][j] = 0.f;

    int buf = 0;
    for (int k0 = 8; k0 <= K; k0 += 8) {
        float4 a2, b2;
        const bool more = (k0 < K);
        if (more) {
            a2 = *(const float4*)(Aptr + k0);
            b2 = bvalid ? *(const float4*)(Bptr + k0) : make_float4(0.f, 0.f, 0.f, 0.f);
        }
#pragma unroll
        for (int kk = 0; kk < 8; kk++) {
            float4 a0 = *(const float4*)&As[buf][kk][ty * 8];
            float4 a1 = *(const float4*)&As[buf][kk][ty * 8 + 4];
            float4 b0 = *(const float4*)&Bs[buf][kk][tx * 8];
            float4 b1 = *(const float4*)&Bs[buf][kk][tx * 8 + 4];
            float a[8] = {a0.x, a0.y, a0.z, a0.w, a1.x, a1.y, a1.z, a1.w};
            float b[8] = {b0.x, b0.y, b0.z, b0.w, b1.x, b1.y, b1.z, b1.w};
#pragma unroll
            for (int i = 0; i < 8; i++)
#pragma unroll
                for (int j = 0; j < 8; j++) acc[i][j] += a[i] * b[j];
        }
        if (more) {
            int nb = buf ^ 1;
            As[nb][lcol + 0][lrow] = a2.x; As[nb][lcol + 1][lrow] = a2.y;
            As[nb][lcol + 2][lrow] = a2.z; As[nb][lcol + 3][lrow] = a2.w;
            Bs[nb][lcol + 0][lrow] = b2.x; Bs[nb][lcol + 1][lrow] = b2.y;
            Bs[nb][lcol + 2][lrow] = b2.z; Bs[nb][lcol + 3][lrow] = b2.w;
            __syncthreads();
            buf = nb;
        }
    }

    if (mode == 0) {
#pragma unroll
        for (int i = 0; i < 8; i++) {
            int m = m0 + ty * 8 + i;
#pragma unroll
            for (int jg = 0; jg < 8; jg += 4) {
                int n = n0 + tx * 8 + jg;
                if (n < N) {
                    float4 v = make_float4(acc[i][jg], acc[i][jg + 1],
                                           acc[i][jg + 2], acc[i][jg + 3]);
                    if (bias1) {
                        float4 bb = *(const float4*)&bias1[n];
                        v.x += bb.x; v.y += bb.y; v.z += bb.z; v.w += bb.w;
                    }
                    if (bias2) {
                        float4 bb = *(const float4*)&bias2[n];
                        v.x += bb.x; v.y += bb.y; v.z += bb.z; v.w += bb.w;
                    }
                    *(float4*)&C[(size_t)m * N + n] = v;
                }
            }
        }
    } else {
        // m = b*128 + t; m-block covers exactly one b
        int b = m0 >> 7;
        int tbase = ty * 8;
#pragma unroll
        for (int j = 0; j < 8; j++) {
            int n = n0 + tx * 8 + j;
            float bb = bias1 ? bias1[n] : 0.f;
            size_t base = ((size_t)b * N + n) * TSZ + tbase;
            float4 v0 = make_float4(acc[0][j] + bb, acc[1][j] + bb,
                                    acc[2][j] + bb, acc[3][j] + bb);
            float4 v1 = make_float4(acc[4][j] + bb, acc[5][j] + bb,
                                    acc[6][j] + bb, acc[7][j] + bb);
            *(float4*)&C[base] = v0;
            *(float4*)&C[base + 4] = v1;
        }
    }
}

// ---------------- fused LSTM step ----------------
__device__ __forceinline__ float sigf(float z) { return 1.f / (1.f + expf(-z)); }

__global__ __launch_bounds__(256)
void lstm_step_k(const float* __restrict__ pre, const float* __restrict__ Wt,
                 const float* __restrict__ hin, float* __restrict__ hout,
                 float* __restrict__ cT, float* __restrict__ y,
                 int Hp, int Gp, int ldy, int t) {
    int r = threadIdx.x & 31;   // permuted column within block: g*8+u
    int s = threadIdx.x >> 5;   // k-slice 0..7
    int col = blockIdx.x * 32 + r;

    float acc[16];
#pragma unroll
    for (int i = 0; i < 16; i++) acc[i] = 0.f;

    const float4* hv4 = (const float4*)hin;  // hin[k*16 + b]
#pragma unroll 2
    for (int k = s; k < Hp; k += 8) {
        float w = Wt[(size_t)k * Gp + col];
        float4 h0 = hv4[k * 4 + 0];
        float4 h1 = hv4[k * 4 + 1];
        float4 h2 = hv4[k * 4 + 2];
        float4 h3 = hv4[k * 4 + 3];
        acc[0]  += w * h0.x; acc[1]  += w * h0.y; acc[2]  += w * h0.z; acc[3]  += w * h0.w;
        acc[4]  += w * h1.x; acc[5]  += w * h1.y; acc[6]  += w * h1.z; acc[7]  += w * h1.w;
        acc[8]  += w * h2.x; acc[9]  += w * h2.y; acc[10] += w * h2.z; acc[11] += w * h2.w;
        acc[12] += w * h3.x; acc[13] += w * h3.y; acc[14] += w * h3.z; acc[15] += w * h3.w;
    }

    __shared__ float red[8][32][16];
    float4* rp = (float4*)&red[s][r][0];
    rp[0] = make_float4(acc[0], acc[1], acc[2], acc[3]);
    rp[1] = make_float4(acc[4], acc[5], acc[6], acc[7]);
    rp[2] = make_float4(acc[8], acc[9], acc[10], acc[11]);
    rp[3] = make_float4(acc[12], acc[13], acc[14], acc[15]);
    __syncthreads();

    if (threadIdx.x < 128) {
        int u = threadIdx.x >> 4;   // unit within block
        int b = threadIdx.x & 15;   // batch
        int j = blockIdx.x * 8 + u;
        if (j < Hp) {
            int G = 4 * Hp;
            size_t row = (size_t)b * TSZ + t;
            const float* prow = pre + row * G + j;
            float gv[4];
#pragma unroll
            for (int g = 0; g < 4; g++) {
                float sum = prow[(size_t)g * Hp];
#pragma unroll
                for (int s2 = 0; s2 < 8; s2++) sum += red[s2][g * 8 + u][b];
                gv[g] = sum;
            }
            float ig = sigf(gv[0]);
            float fg = sigf(gv[1]);
            float gg = tanhf(gv[2]);
            float og = sigf(gv[3]);
            float c  = fg * cT[j * 16 + b] + ig * gg;
            float hn = og * tanhf(c);
            cT[j * 16 + b]   = c;
            hout[j * 16 + b] = hn;
            y[row * ldy + j] = hn;
        }
    }
}

// ---------------- finalize: pack h1..h3, c1..c3 behind logits ----------------
__global__ void finalize_k(const float* __restrict__ y1, const float* __restrict__ y2,
                           const float* __restrict__ y3, const float* __restrict__ cT1,
                           const float* __restrict__ cT2, const float* __restrict__ cT3,
                           float* __restrict__ out) {
    int i = blockIdx.x * blockDim.x + threadIdx.x;
    if (i >= 86400) return;
    const size_t O = (size_t)BSZ * VSZ * TSZ;
    if (i < 18400) {
        int b = i / 1150, j = i % 1150;
        out[O + i] = y1[((size_t)b * TSZ + 127) * HPAD + j];
    } else if (i < 36800) {
        int k = i - 18400; int b = k / 1150, j = k % 1150;
        out[O + i] = y2[((size_t)b * TSZ + 127) * HPAD + j];
    } else if (i < 43200) {
        int k = i - 36800; int b = k / 400, j = k % 400;
        out[O + i] = y3[((size_t)b * TSZ + 127) * 400 + j];
    } else if (i < 61600) {
        int k = i - 43200; int j = (k % 1150), b = k / 1150;
        out[O + i] = cT1[j * 16 + b];
    } else if (i < 80000) {
        int k = i - 61600; int j = (k % 1150), b = k / 1150;
        out[O + i] = cT2[j * 16 + b];
    } else {
        int k = i - 80000; int j = (k % 400), b = k / 400;
        out[O + i] = cT3[j * 16 + b];
    }
}

// ---------------- launch ----------------
extern "C" void kernel_launch(void* const* d_in, const int* in_sizes, int n_in,
                              void* d_out, int out_size) {
    const float* emb  = (const float*)d_in[0];
    const float* Wih1 = (const float*)d_in[1];
    const float* Whh1 = (const float*)d_in[2];
    const float* bih1 = (const float*)d_in[3];
    const float* bhh1 = (const float*)d_in[4];
    const float* Wih2 = (const float*)d_in[5];
    const float* Whh2 = (const float*)d_in[6];
    const float* bih2 = (const float*)d_in[7];
    const float* bhh2 = (const float*)d_in[8];
    const float* Wih3 = (const float*)d_in[9];
    const float* Whh3 = (const float*)d_in[10];
    const float* bih3 = (const float*)d_in[11];
    const float* bhh3 = (const float*)d_in[12];
    const float* linb = (const float*)d_in[13];
    const int*   x    = (const int*)d_in[14];
    float* out = (float*)d_out;

    float *y0, *y1, *y2, *y3, *pre, *Wt1, *Wt2, *Wt3, *W2p, *W3p;
    float *hTa, *hTb, *cT1, *cT2, *cT3;
    cudaGetSymbolAddress((void**)&y0,  g_y0);
    cudaGetSymbolAddress((void**)&y1,  g_y1);
    cudaGetSymbolAddress((void**)&y2,  g_y2);
    cudaGetSymbolAddress((void**)&y3,  g_y3);
    cudaGetSymbolAddress((void**)&pre, g_pre);
    cudaGetSymbolAddress((void**)&Wt1, g_Wt1);
    cudaGetSymbolAddress((void**)&Wt2, g_Wt2);
    cudaGetSymbolAddress((void**)&Wt3, g_Wt3);
    cudaGetSymbolAddress((void**)&W2p, g_Wih2p);
    cudaGetSymbolAddress((void**)&W3p, g_Wih3p);
    cudaGetSymbolAddress((void**)&hTa, g_hTa);
    cudaGetSymbolAddress((void**)&hTb, g_hTb);
    cudaGetSymbolAddress((void**)&cT1, g_cT1);
    cudaGetSymbolAddress((void**)&cT2, g_cT2);
    cudaGetSymbolAddress((void**)&cT3, g_cT3);

    const int M = TSZ * BSZ;  // 2048

    // setup: embedding, weight transposes/pads, zeroing
    embed_k<<<(TSZ * BSZ * ESZ + 255) / 256, 256>>>(emb, x, y0);
    wtrans_k<<<dim3(GP12 / 32, (HSZ + 31) / 32), dim3(32, 8)>>>(Whh1, Wt1, HSZ, GP12);
    wtrans_k<<<dim3(GP12 / 32, (HSZ + 31) / 32), dim3(32, 8)>>>(Whh2, Wt2, HSZ, GP12);
    wtrans_k<<<dim3(GP3 / 32, (ESZ + 31) / 32), dim3(32, 8)>>>(Whh3, Wt3, ESZ, GP3);
    pad_k<<<(4 * HSZ * HPAD + 255) / 256, 256>>>(Wih2, W2p, 4 * HSZ, HSZ, HPAD);
    pad_k<<<(4 * ESZ * HPAD + 255) / 256, 256>>>(Wih3, W3p, 4 * ESZ, HSZ, HPAD);
    zero_k<<<(M * HPAD + 255) / 256, 256>>>(y1, M * HPAD);
    zero_k<<<(M * HPAD + 255) / 256, 256>>>(y2, M * HPAD);
    zero_k<<<(HSZ * BSZ + 255) / 256, 256>>>(cT1, HSZ * BSZ);
    zero_k<<<(HSZ * BSZ + 255) / 256, 256>>>(cT2, HSZ * BSZ);
    zero_k<<<(ESZ * BSZ + 255) / 256, 256>>>(cT3, ESZ * BSZ);

    // ----- layer 1 -----
    gemm_k<<<dim3((4 * HSZ + 127) / 128, M / 128), 256>>>(y0, Wih1, bih1, bhh1, pre,
                                                          M, 4 * HSZ, ESZ, 0);
    zero_k<<<(HSZ * BSZ + 255) / 256, 256>>>(hTa, HSZ * BSZ);
    for (int t = 0; t < TSZ; t++) {
        float* hin  = (t & 1) ? hTb : hTa;
        float* hout = (t & 1) ? hTa : hTb;
        lstm_step_k<<<GP12 / 32, 256>>>(pre, Wt1, hin, hout, cT1, y1, HSZ, GP12, HPAD, t);
    }

    // ----- layer 2 -----
    gemm_k<<<dim3((4 * HSZ + 127) / 128, M / 128), 256>>>(y1, W2p, bih2, bhh2, pre,
                                                          M, 4 * HSZ, HPAD, 0);
    zero_k<<<(HSZ * BSZ + 255) / 256, 256>>>(hTa, HSZ * BSZ);
    for (int t = 0; t < TSZ; t++) {
        float* hin  = (t & 1) ? hTb : hTa;
        float* hout = (t & 1) ? hTa : hTb;
        lstm_step_k<<<GP12 / 32, 256>>>(pre, Wt2, hin, hout, cT2, y2, HSZ, GP12, HPAD, t);
    }

    // ----- layer 3 -----
    gemm_k<<<dim3((4 * ESZ + 127) / 128, M / 128), 256>>>(y2, W3p, bih3, bhh3, pre,
                                                          M, 4 * ESZ, HPAD, 0);
    zero_k<<<(ESZ * BSZ + 255) / 256, 256>>>(hTa, ESZ * BSZ);
    for (int t = 0; t < TSZ; t++) {
        float* hin  = (t & 1) ? hTb : hTa;
        float* hout = (t & 1) ? hTa : hTb;
        lstm_step_k<<<GP3 / 32, 256>>>(pre, Wt3, hin, hout, cT3, y3, ESZ, GP3, ESZ, t);
    }

    // ----- tied output projection into (B,V,T) -----
    gemm_k<<<dim3(VSZ / 128, M / 128), 256>>>(y3, emb, linb, nullptr, out,
                                              M, VSZ, ESZ, 1);

    // ----- final states -----
    finalize_k<<<(86400 + 255) / 256, 256>>>(y1, y2, y3, cT1, cT2, cT3, out);
}